// round 1
// baseline (speedup 1.0000x reference)
#include <cuda_runtime.h>
#include <math.h>
#include <stdint.h>

#define N_NODES 100000
#define N_EDGES 1600000
#define DIM 128
#define NL 3
#define NG 256
#define BN_EPS 1e-5f
#define LN_EPS 1e-5f

// ---------------- scratch (static device globals; no allocation) ----------------
__device__ __align__(16) float d_A[N_NODES * DIM];   // current node features (layer output)
__device__ __align__(16) float d_Bagg[N_NODES * DIM]; // (1+eps)*x + scatter-sum
__device__ __align__(16) float d_C[N_NODES * DIM];   // post-GEMM1 hidden
__device__ float d_stats[NL * 2 * DIM];              // per-layer BN sum / sumsq
__device__ float d_gmax[NG * DIM];
__device__ float d_gsum[NG * DIM];
__device__ int   d_gcnt[NG];
__device__ int   d_ei64;   // 1 if edge_index is int64
__device__ int   d_b64;    // 1 if batch is int64

// ---------------- init ----------------
__global__ void k_init() {
    int i = blockIdx.x * blockDim.x + threadIdx.x;   // grid covers 32768
    if (i < NL * 2 * DIM) d_stats[i] = 0.f;
    if (i < NG * DIM) { d_gmax[i] = -INFINITY; d_gsum[i] = 0.f; }
    if (i < NG) d_gcnt[i] = 0;
}

// ---------------- dtype probe (int32 vs int64) ----------------
__global__ void k_detect(const int* __restrict__ ei, const int* __restrict__ batch) {
    __shared__ int s1, s2;
    if (threadIdx.x == 0) { s1 = 0; s2 = 0; }
    __syncthreads();
    for (int i = threadIdx.x; i < 10000; i += blockDim.x) {
        // if data is int64, word (2i+1) is the high word of element i (values < 2^31 -> 0)
        if (ei[2 * i + 1] != 0)    atomicOr(&s1, 1);
        if (batch[2 * i + 1] != 0) atomicOr(&s2, 1);
    }
    __syncthreads();
    if (threadIdx.x == 0) { d_ei64 = s1 ? 0 : 1; d_b64 = s2 ? 0 : 1; }
}

// ---------------- pre-aggregation: Bagg = (1+eps_l) * cur ----------------
__global__ void k_preagg(const float* __restrict__ x, const float* __restrict__ geps, int l) {
    const float* cur = (l == 0) ? x : d_A;
    int i = blockIdx.x * blockDim.x + threadIdx.x;   // float4 index
    if (i >= N_NODES * DIM / 4) return;
    float s = 1.f + geps[l];
    float4 v = ((const float4*)cur)[i];
    v.x *= s; v.y *= s; v.z *= s; v.w *= s;
    ((float4*)d_Bagg)[i] = v;
}

// ---------------- edge scatter: Bagg[dst] += cur[src], warp-per-edge ----------------
__global__ void k_scatter(const float* __restrict__ x, const int* __restrict__ ei, int l) {
    const float* cur = (l == 0) ? x : d_A;
    int w = (blockIdx.x * blockDim.x + threadIdx.x) >> 5;
    int lane = threadIdx.x & 31;
    if (w >= N_EDGES) return;
    int src, dst;
    if (d_ei64) {
        const long long* e64 = (const long long*)ei;
        src = (int)e64[w];
        dst = (int)e64[N_EDGES + w];
    } else {
        src = ei[w];
        dst = ei[N_EDGES + w];
    }
    float4 v = ((const float4*)(cur + (size_t)src * DIM))[lane];
    float* p = d_Bagg + (size_t)dst * DIM + lane * 4;
    asm volatile("red.global.add.v4.f32 [%0], {%1,%2,%3,%4};"
                 :: "l"(p), "f"(v.x), "f"(v.y), "f"(v.z), "f"(v.w) : "memory");
}

// ---------------- GEMM1: C = Bagg @ W1[l] + b1[l], fused BN-stat accumulation ----------------
// 128x128 tile per block, 256 threads, 8x8 register tile, K=128 in one slab.
__global__ void __launch_bounds__(256, 1)
k_gemm_bn(const float* __restrict__ W, const float* __restrict__ bias, int l) {
    extern __shared__ float smem[];
    float* As = smem;            // 128*128
    float* Bs = smem + 16384;    // 128*128
    const float* X = d_Bagg;
    int tid = threadIdx.x;
    int row0 = blockIdx.x * 128;

    #pragma unroll
    for (int i = 0; i < 16; i++) {
        int idx = tid + i * 256;
        ((float4*)Bs)[idx] = ((const float4*)W)[idx];
    }
    #pragma unroll
    for (int i = 0; i < 16; i++) {
        int idx = tid + i * 256;
        int r = idx >> 5, c4 = idx & 31;
        int grow = row0 + r;
        float4 v = make_float4(0.f, 0.f, 0.f, 0.f);
        if (grow < N_NODES) v = ((const float4*)X)[grow * 32 + c4];
        ((float4*)As)[idx] = v;
    }
    __syncthreads();

    int tx = tid & 15, ty = tid >> 4;
    float acc[8][8];
    #pragma unroll
    for (int i = 0; i < 8; i++)
        #pragma unroll
        for (int j = 0; j < 8; j++) acc[i][j] = 0.f;

    const float* Ab = As + ty * 8 * 128;
    const float* Bb = Bs + tx * 8;
    #pragma unroll 8
    for (int k = 0; k < 128; k++) {
        float4 bq0 = *(const float4*)(Bb + k * 128);
        float4 bq1 = *(const float4*)(Bb + k * 128 + 4);
        float bv[8] = {bq0.x, bq0.y, bq0.z, bq0.w, bq1.x, bq1.y, bq1.z, bq1.w};
        #pragma unroll
        for (int i = 0; i < 8; i++) {
            float a = Ab[i * 128 + k];
            #pragma unroll
            for (int j = 0; j < 8; j++) acc[i][j] = fmaf(a, bv[j], acc[i][j]);
        }
    }
    __syncthreads();   // done reading As; reuse it for the reduction below

    float bl[8];
    #pragma unroll
    for (int j = 0; j < 8; j++) bl[j] = bias[tx * 8 + j];
    float cs[8], cq[8];
    #pragma unroll
    for (int j = 0; j < 8; j++) { cs[j] = 0.f; cq[j] = 0.f; }

    #pragma unroll
    for (int i = 0; i < 8; i++) {
        int grow = row0 + ty * 8 + i;
        if (grow < N_NODES) {
            #pragma unroll
            for (int j = 0; j < 8; j++) {
                float v = acc[i][j] + bl[j];
                acc[i][j] = v;
                cs[j] += v;
                cq[j] += v * v;
            }
            float4 s0 = make_float4(acc[i][0], acc[i][1], acc[i][2], acc[i][3]);
            float4 s1 = make_float4(acc[i][4], acc[i][5], acc[i][6], acc[i][7]);
            float* op = d_C + (size_t)grow * 128 + tx * 8;
            ((float4*)op)[0] = s0;
            ((float4*)(op + 4))[0] = s1;
        }
    }

    float* rs = As;               // [16][128]
    float* rq = As + 16 * 128;    // [16][128]
    #pragma unroll
    for (int j = 0; j < 8; j++) {
        rs[ty * 128 + tx * 8 + j] = cs[j];
        rq[ty * 128 + tx * 8 + j] = cq[j];
    }
    __syncthreads();
    if (tid < 128) {
        float s = 0.f, q = 0.f;
        #pragma unroll
        for (int t = 0; t < 16; t++) { s += rs[t * 128 + tid]; q += rq[t * 128 + tid]; }
        atomicAdd(&d_stats[l * 2 * DIM + tid], s);
        atomicAdd(&d_stats[l * 2 * DIM + DIM + tid], q);
    }
}

// ---------------- GEMM2: A = leaky(LN( relu(BN(C)) @ W2[l] + b2[l] )) ----------------
__global__ void __launch_bounds__(256, 1)
k_gemm_ln(const float* __restrict__ W, const float* __restrict__ b2,
          const float* __restrict__ bn_g, const float* __restrict__ bn_b,
          const float* __restrict__ ln_g, const float* __restrict__ ln_b, int l) {
    extern __shared__ float smem[];
    float* As    = smem;              // 128*128
    float* Bs    = smem + 16384;      // 128*128
    float* aff_a = smem + 32768;      // 128
    float* aff_b = aff_a + 128;       // 128
    float* s_lng = aff_b + 128;       // 128
    float* s_lnb = s_lng + 128;       // 128
    const float* X = d_C;
    int tid = threadIdx.x;
    int row0 = blockIdx.x * 128;

    if (tid < 128) {
        float mu  = d_stats[l * 2 * DIM + tid] * (1.f / N_NODES);
        float var = d_stats[l * 2 * DIM + DIM + tid] * (1.f / N_NODES) - mu * mu;
        float rstd = rsqrtf(var + BN_EPS);
        float a = bn_g[tid] * rstd;
        aff_a[tid] = a;
        aff_b[tid] = bn_b[tid] - mu * a;
        s_lng[tid] = ln_g[tid];
        s_lnb[tid] = ln_b[tid];
    }
    __syncthreads();

    #pragma unroll
    for (int i = 0; i < 16; i++) {
        int idx = tid + i * 256;
        ((float4*)Bs)[idx] = ((const float4*)W)[idx];
    }
    #pragma unroll
    for (int i = 0; i < 16; i++) {
        int idx = tid + i * 256;
        int r = idx >> 5, c4 = idx & 31;
        int grow = row0 + r;
        float4 v = make_float4(0.f, 0.f, 0.f, 0.f);
        if (grow < N_NODES) v = ((const float4*)X)[grow * 32 + c4];
        int k0 = c4 * 4;
        v.x = fmaxf(fmaf(v.x, aff_a[k0 + 0], aff_b[k0 + 0]), 0.f);
        v.y = fmaxf(fmaf(v.y, aff_a[k0 + 1], aff_b[k0 + 1]), 0.f);
        v.z = fmaxf(fmaf(v.z, aff_a[k0 + 2], aff_b[k0 + 2]), 0.f);
        v.w = fmaxf(fmaf(v.w, aff_a[k0 + 3], aff_b[k0 + 3]), 0.f);
        ((float4*)As)[idx] = v;
    }
    __syncthreads();

    int tx = tid & 15, ty = tid >> 4;
    float acc[8][8];
    #pragma unroll
    for (int i = 0; i < 8; i++)
        #pragma unroll
        for (int j = 0; j < 8; j++) acc[i][j] = 0.f;

    const float* Ab = As + ty * 8 * 128;
    const float* Bb = Bs + tx * 8;
    #pragma unroll 8
    for (int k = 0; k < 128; k++) {
        float4 bq0 = *(const float4*)(Bb + k * 128);
        float4 bq1 = *(const float4*)(Bb + k * 128 + 4);
        float bv[8] = {bq0.x, bq0.y, bq0.z, bq0.w, bq1.x, bq1.y, bq1.z, bq1.w};
        #pragma unroll
        for (int i = 0; i < 8; i++) {
            float a = Ab[i * 128 + k];
            #pragma unroll
            for (int j = 0; j < 8; j++) acc[i][j] = fmaf(a, bv[j], acc[i][j]);
        }
    }
    __syncthreads();  // done reading As

    float b2l[8];
    #pragma unroll
    for (int j = 0; j < 8; j++) b2l[j] = b2[tx * 8 + j];

    float rsum[8], rsq[8];
    #pragma unroll
    for (int i = 0; i < 8; i++) { rsum[i] = 0.f; rsq[i] = 0.f; }
    #pragma unroll
    for (int i = 0; i < 8; i++) {
        #pragma unroll
        for (int j = 0; j < 8; j++) {
            float v = acc[i][j] + b2l[j];
            acc[i][j] = v;
            rsum[i] += v;
            rsq[i]  += v * v;
        }
    }

    float* redS = As;               // [128][16]
    float* redQ = As + 2048;        // [128][16]
    float* rowM = As + 4096;        // [128]
    float* rowR = As + 4224;        // [128]
    #pragma unroll
    for (int i = 0; i < 8; i++) {
        redS[(ty * 8 + i) * 16 + tx] = rsum[i];
        redQ[(ty * 8 + i) * 16 + tx] = rsq[i];
    }
    __syncthreads();
    if (tid < 128) {
        float s = 0.f, q = 0.f;
        #pragma unroll
        for (int t = 0; t < 16; t++) { s += redS[tid * 16 + t]; q += redQ[tid * 16 + t]; }
        float m = s * (1.f / 128.f);
        float v = q * (1.f / 128.f) - m * m;
        rowM[tid] = m;
        rowR[tid] = rsqrtf(v + LN_EPS);
    }
    __syncthreads();

    #pragma unroll
    for (int i = 0; i < 8; i++) {
        int grow = row0 + ty * 8 + i;
        if (grow < N_NODES) {
            float m = rowM[ty * 8 + i];
            float r = rowR[ty * 8 + i];
            #pragma unroll
            for (int j = 0; j < 8; j++) {
                int c = tx * 8 + j;
                float h = (acc[i][j] - m) * r * s_lng[c] + s_lnb[c];
                acc[i][j] = (h >= 0.f) ? h : 0.1f * h;
            }
            float4 s0 = make_float4(acc[i][0], acc[i][1], acc[i][2], acc[i][3]);
            float4 s1 = make_float4(acc[i][4], acc[i][5], acc[i][6], acc[i][7]);
            float* op = d_A + (size_t)grow * 128 + tx * 8;
            ((float4*)op)[0] = s0;
            ((float4*)(op + 4))[0] = s1;
        }
    }
}

// ---------------- pooling: sorted-batch segment max/sum/count ----------------
__device__ __forceinline__ void atomicMaxFloat(float* addr, float val) {
    if (val >= 0.f) atomicMax((int*)addr, __float_as_int(val));
    else            atomicMin((unsigned int*)addr, __float_as_uint(val));
}

#define PROWS 512
__global__ void k_pool(const int* __restrict__ batch) {
    __shared__ int sb[PROWS];
    int r0 = blockIdx.x * PROWS;
    int r1 = min(r0 + PROWS, N_NODES);
    int c = threadIdx.x;  // 128 threads: one feature column each
    int is64 = d_b64;
    for (int r = r0 + threadIdx.x; r < r1; r += 128)
        sb[r - r0] = is64 ? (int)((const long long*)batch)[r] : batch[r];
    __syncthreads();

    int gcur = -1, cnt = 0;
    float mx = -INFINITY, smv = 0.f;
    for (int r = r0; r < r1; r++) {
        int g = sb[r - r0];
        if (g != gcur) {
            if (gcur >= 0) {
                atomicMaxFloat(&d_gmax[gcur * 128 + c], mx);
                atomicAdd(&d_gsum[gcur * 128 + c], smv);
                if (c == 0) atomicAdd(&d_gcnt[gcur], cnt);
            }
            gcur = g; mx = -INFINITY; smv = 0.f; cnt = 0;
        }
        float v = d_A[(size_t)r * 128 + c];
        mx = fmaxf(mx, v);
        smv += v;
        cnt++;
    }
    if (gcur >= 0) {
        atomicMaxFloat(&d_gmax[gcur * 128 + c], mx);
        atomicAdd(&d_gsum[gcur * 128 + c], smv);
        if (c == 0) atomicAdd(&d_gcnt[gcur], cnt);
    }
}

// ---------------- final projection: out = [gmax || gmean] @ Wout + bout ----------------
__global__ void k_final(const float* __restrict__ Wout, const float* __restrict__ bout,
                        float* __restrict__ out) {
    __shared__ float pm[128], pa[128];
    int g = blockIdx.x, j = threadIdx.x;
    float cf = fmaxf((float)d_gcnt[g], 1.f);
    pm[j] = d_gmax[g * 128 + j];
    pa[j] = d_gsum[g * 128 + j] / cf;
    __syncthreads();
    float acc = bout[j];
    #pragma unroll 4
    for (int k = 0; k < 128; k++) acc = fmaf(pm[k], Wout[k * 128 + j], acc);
    #pragma unroll 4
    for (int k = 0; k < 128; k++) acc = fmaf(pa[k], Wout[(k + 128) * 128 + j], acc);
    out[g * 128 + j] = acc;
}

// ---------------- host launch ----------------
extern "C" void kernel_launch(void* const* d_in, const int* in_sizes, int n_in,
                              void* d_out, int out_size) {
    const float* x    = (const float*)d_in[0];
    const float* W1   = (const float*)d_in[1];
    const float* b1   = (const float*)d_in[2];
    const float* bn_g = (const float*)d_in[3];
    const float* bn_b = (const float*)d_in[4];
    const float* W2   = (const float*)d_in[5];
    const float* b2   = (const float*)d_in[6];
    const float* geps = (const float*)d_in[7];
    const float* ln_g = (const float*)d_in[8];
    const float* ln_b = (const float*)d_in[9];
    const float* Wout = (const float*)d_in[10];
    const float* bout = (const float*)d_in[11];
    const int*   ei   = (const int*)d_in[12];
    const int*   batch= (const int*)d_in[13];
    float* out = (float*)d_out;

    const int SMEMSZ = 136 * 1024;
    cudaFuncSetAttribute(k_gemm_bn, cudaFuncAttributeMaxDynamicSharedMemorySize, SMEMSZ);
    cudaFuncSetAttribute(k_gemm_ln, cudaFuncAttributeMaxDynamicSharedMemorySize, SMEMSZ);

    k_init<<<128, 256>>>();
    k_detect<<<1, 256>>>(ei, batch);

    const int NBLK = (N_NODES + 127) / 128;          // 782
    for (int l = 0; l < NL; l++) {
        k_preagg<<<(N_NODES * DIM / 4 + 255) / 256, 256>>>(x, geps, l);
        k_scatter<<<(N_EDGES * 32 + 255) / 256, 256>>>(x, ei, l);
        k_gemm_bn<<<NBLK, 256, SMEMSZ>>>(W1 + (size_t)l * DIM * DIM, b1 + l * DIM, l);
        k_gemm_ln<<<NBLK, 256, SMEMSZ>>>(W2 + (size_t)l * DIM * DIM, b2 + l * DIM,
                                         bn_g + l * DIM, bn_b + l * DIM,
                                         ln_g + l * DIM, ln_b + l * DIM, l);
    }
    k_pool<<<(N_NODES + PROWS - 1) / PROWS, 128>>>(batch);
    k_final<<<NG, 128>>>(Wout, bout, out);
}

// round 2
// speedup vs baseline: 1.2172x; 1.2172x over previous
#include <cuda_runtime.h>
#include <math.h>
#include <stdint.h>

#define N_NODES 100000
#define N_EDGES 1600000
#define DIM 128
#define NL 3
#define NG 256
#define BN_EPS 1e-5f
#define LN_EPS 1e-5f

// ---------------- scratch (static device globals; no allocation) ----------------
__device__ __align__(16) float d_A[N_NODES * DIM];    // current node features (layer output)
__device__ __align__(16) float d_Bagg[N_NODES * DIM]; // (1+eps)*x + neighbor sum
__device__ __align__(16) float d_C[N_NODES * DIM];    // post-GEMM1 hidden
__device__ float d_stats[NL * 2 * DIM];               // per-layer BN sum / sumsq
__device__ float d_gmax[NG * DIM];
__device__ float d_gsum[NG * DIM];
__device__ int   d_gcnt[NG];
__device__ int   d_ei64;   // 1 if edge_index is int64
__device__ int   d_b64;    // 1 if batch is int64
// CSR scratch
__device__ int d_deg[N_NODES];
__device__ int d_off[N_NODES + 1];
__device__ int d_cur[N_NODES];
__device__ int d_csr[N_EDGES];

// ---------------- f32x2 helpers ----------------
__device__ __forceinline__ unsigned long long pack2(float a) {
    unsigned long long r;
    asm("mov.b64 %0, {%1, %1};" : "=l"(r) : "f"(a));
    return r;
}
__device__ __forceinline__ void ffma2(unsigned long long& d, unsigned long long a,
                                      unsigned long long b) {
    asm("fma.rn.f32x2 %0, %1, %2, %0;" : "+l"(d) : "l"(a), "l"(b));
}
__device__ __forceinline__ float2 unpack2(unsigned long long u) {
    float2 f;
    asm("mov.b64 {%0, %1}, %2;" : "=f"(f.x), "=f"(f.y) : "l"(u));
    return f;
}

// ---------------- init ----------------
__global__ void k_init() {
    int i = blockIdx.x * blockDim.x + threadIdx.x;
    if (i < NL * 2 * DIM) d_stats[i] = 0.f;
    if (i < NG * DIM) { d_gmax[i] = -INFINITY; d_gsum[i] = 0.f; }
    if (i < NG) d_gcnt[i] = 0;
    if (i < N_NODES) d_deg[i] = 0;
}

// ---------------- dtype probe (int32 vs int64) ----------------
__global__ void k_detect(const int* __restrict__ ei, const int* __restrict__ batch) {
    __shared__ int s1, s2;
    if (threadIdx.x == 0) { s1 = 0; s2 = 0; }
    __syncthreads();
    for (int i = threadIdx.x; i < 10000; i += blockDim.x) {
        if (ei[2 * i + 1] != 0)    atomicOr(&s1, 1);
        if (batch[2 * i + 1] != 0) atomicOr(&s2, 1);
    }
    __syncthreads();
    if (threadIdx.x == 0) { d_ei64 = s1 ? 0 : 1; d_b64 = s2 ? 0 : 1; }
}

// ---------------- CSR build ----------------
__global__ void k_hist(const int* __restrict__ ei) {
    int i = blockIdx.x * blockDim.x + threadIdx.x;
    if (i >= N_EDGES) return;
    int dst;
    if (d_ei64) dst = (int)((const long long*)ei)[N_EDGES + i];
    else        dst = ei[N_EDGES + i];
    atomicAdd(&d_deg[dst], 1);
}

__global__ void k_scan() {
    __shared__ int ssum[1024];
    int t = threadIdx.x;
    const int CH = (N_NODES + 1023) / 1024;   // 98
    int beg = t * CH, end = min(beg + CH, N_NODES);
    int s = 0;
    for (int i = beg; i < end; i++) s += d_deg[i];
    ssum[t] = s;
    __syncthreads();
    // inclusive Hillis-Steele scan
    for (int off = 1; off < 1024; off <<= 1) {
        int v = (t >= off) ? ssum[t - off] : 0;
        __syncthreads();
        ssum[t] += v;
        __syncthreads();
    }
    int run = (t == 0) ? 0 : ssum[t - 1];
    for (int i = beg; i < end; i++) {
        d_off[i] = run;
        d_cur[i] = run;
        run += d_deg[i];
    }
    if (t == 0) d_off[N_NODES] = ssum[1023];
}

__global__ void k_fill(const int* __restrict__ ei) {
    int i = blockIdx.x * blockDim.x + threadIdx.x;
    if (i >= N_EDGES) return;
    int src, dst;
    if (d_ei64) {
        const long long* e64 = (const long long*)ei;
        src = (int)e64[i];
        dst = (int)e64[N_EDGES + i];
    } else {
        src = ei[i];
        dst = ei[N_EDGES + i];
    }
    int pos = atomicAdd(&d_cur[dst], 1);
    d_csr[pos] = src;
}

// ---------------- aggregation: warp per node, register accumulation ----------------
__global__ void k_agg(const float* __restrict__ x, const float* __restrict__ geps, int l) {
    int w = (blockIdx.x * blockDim.x + threadIdx.x) >> 5;
    int lane = threadIdx.x & 31;
    if (w >= N_NODES) return;
    const float* cur = (l == 0) ? x : d_A;
    float s = 1.f + geps[l];
    float4 acc = ((const float4*)cur)[(size_t)w * 32 + lane];
    acc.x *= s; acc.y *= s; acc.z *= s; acc.w *= s;
    int beg = d_off[w], end = d_off[w + 1];
    for (int base = beg; base < end; base += 32) {
        int idx = 0;
        if (base + lane < end) idx = d_csr[base + lane];
        int n = min(32, end - base);
        for (int t = 0; t < n; t++) {
            int sidx = __shfl_sync(0xffffffff, idx, t);
            float4 v = ((const float4*)cur)[(size_t)sidx * 32 + lane];
            acc.x += v.x; acc.y += v.y; acc.z += v.z; acc.w += v.w;
        }
    }
    ((float4*)d_Bagg)[(size_t)w * 32 + lane] = acc;
}

// ---------------- GEMM1: C = Bagg @ W1[l] + b1[l], fused BN-stat accumulation ----------------
// 128x128 tile per block, 256 threads, 8x8 register tile (f32x2 packed along j), K=128.
__global__ void __launch_bounds__(256, 1)
k_gemm_bn(const float* __restrict__ W, const float* __restrict__ bias, int l) {
    extern __shared__ float smem[];
    float* As = smem;            // 128*128
    float* Bs = smem + 16384;    // 128*128
    const float* X = d_Bagg;
    int tid = threadIdx.x;
    int row0 = blockIdx.x * 128;

    #pragma unroll
    for (int i = 0; i < 16; i++) {
        int idx = tid + i * 256;
        ((float4*)Bs)[idx] = ((const float4*)W)[idx];
    }
    #pragma unroll
    for (int i = 0; i < 16; i++) {
        int idx = tid + i * 256;
        int r = idx >> 5, c4 = idx & 31;
        int grow = row0 + r;
        float4 v = make_float4(0.f, 0.f, 0.f, 0.f);
        if (grow < N_NODES) v = ((const float4*)X)[grow * 32 + c4];
        ((float4*)As)[idx] = v;
    }
    __syncthreads();

    int tx = tid & 15, ty = tid >> 4;
    unsigned long long acc[8][4];
    #pragma unroll
    for (int i = 0; i < 8; i++)
        #pragma unroll
        for (int j = 0; j < 4; j++) acc[i][j] = 0ULL;

    const float* Ab = As + ty * 8 * 128;
    #pragma unroll 8
    for (int k = 0; k < 128; k++) {
        const unsigned long long* bp = (const unsigned long long*)(Bs + k * 128) + tx * 4;
        ulonglong2 q0 = *(const ulonglong2*)bp;
        ulonglong2 q1 = *(const ulonglong2*)(bp + 2);
        unsigned long long bb0 = q0.x, bb1 = q0.y, bb2 = q1.x, bb3 = q1.y;
        #pragma unroll
        for (int i = 0; i < 8; i++) {
            unsigned long long aa = pack2(Ab[i * 128 + k]);
            ffma2(acc[i][0], aa, bb0);
            ffma2(acc[i][1], aa, bb1);
            ffma2(acc[i][2], aa, bb2);
            ffma2(acc[i][3], aa, bb3);
        }
    }
    __syncthreads();   // done reading As; reuse it below

    float bl[8];
    #pragma unroll
    for (int j = 0; j < 8; j++) bl[j] = bias[tx * 8 + j];
    float cs[8], cq[8];
    #pragma unroll
    for (int j = 0; j < 8; j++) { cs[j] = 0.f; cq[j] = 0.f; }

    #pragma unroll
    for (int i = 0; i < 8; i++) {
        int grow = row0 + ty * 8 + i;
        if (grow < N_NODES) {
            float v[8];
            #pragma unroll
            for (int j4 = 0; j4 < 4; j4++) {
                float2 f = unpack2(acc[i][j4]);
                v[2 * j4] = f.x + bl[2 * j4];
                v[2 * j4 + 1] = f.y + bl[2 * j4 + 1];
            }
            #pragma unroll
            for (int j = 0; j < 8; j++) { cs[j] += v[j]; cq[j] += v[j] * v[j]; }
            float* op = d_C + (size_t)grow * 128 + tx * 8;
            ((float4*)op)[0] = make_float4(v[0], v[1], v[2], v[3]);
            ((float4*)(op + 4))[0] = make_float4(v[4], v[5], v[6], v[7]);
        }
    }

    float* rs = As;               // [16][128]
    float* rq = As + 16 * 128;    // [16][128]
    #pragma unroll
    for (int j = 0; j < 8; j++) {
        rs[ty * 128 + tx * 8 + j] = cs[j];
        rq[ty * 128 + tx * 8 + j] = cq[j];
    }
    __syncthreads();
    if (tid < 128) {
        float s = 0.f, q = 0.f;
        #pragma unroll
        for (int t = 0; t < 16; t++) { s += rs[t * 128 + tid]; q += rq[t * 128 + tid]; }
        atomicAdd(&d_stats[l * 2 * DIM + tid], s);
        atomicAdd(&d_stats[l * 2 * DIM + DIM + tid], q);
    }
}

// ---------------- GEMM2: A = leaky(LN( relu(BN(C)) @ W2[l] + b2[l] )) ----------------
__global__ void __launch_bounds__(256, 1)
k_gemm_ln(const float* __restrict__ W, const float* __restrict__ b2,
          const float* __restrict__ bn_g, const float* __restrict__ bn_b,
          const float* __restrict__ ln_g, const float* __restrict__ ln_b, int l) {
    extern __shared__ float smem[];
    float* As    = smem;              // 128*128
    float* Bs    = smem + 16384;      // 128*128
    float* aff_a = smem + 32768;      // 128
    float* aff_b = aff_a + 128;       // 128
    float* s_lng = aff_b + 128;       // 128
    float* s_lnb = s_lng + 128;       // 128
    const float* X = d_C;
    int tid = threadIdx.x;
    int row0 = blockIdx.x * 128;

    if (tid < 128) {
        float mu  = d_stats[l * 2 * DIM + tid] * (1.f / N_NODES);
        float var = d_stats[l * 2 * DIM + DIM + tid] * (1.f / N_NODES) - mu * mu;
        float rstd = rsqrtf(var + BN_EPS);
        float a = bn_g[tid] * rstd;
        aff_a[tid] = a;
        aff_b[tid] = bn_b[tid] - mu * a;
        s_lng[tid] = ln_g[tid];
        s_lnb[tid] = ln_b[tid];
    }
    __syncthreads();

    #pragma unroll
    for (int i = 0; i < 16; i++) {
        int idx = tid + i * 256;
        ((float4*)Bs)[idx] = ((const float4*)W)[idx];
    }
    #pragma unroll
    for (int i = 0; i < 16; i++) {
        int idx = tid + i * 256;
        int r = idx >> 5, c4 = idx & 31;
        int grow = row0 + r;
        float4 v = make_float4(0.f, 0.f, 0.f, 0.f);
        if (grow < N_NODES) v = ((const float4*)X)[grow * 32 + c4];
        int k0 = c4 * 4;
        v.x = fmaxf(fmaf(v.x, aff_a[k0 + 0], aff_b[k0 + 0]), 0.f);
        v.y = fmaxf(fmaf(v.y, aff_a[k0 + 1], aff_b[k0 + 1]), 0.f);
        v.z = fmaxf(fmaf(v.z, aff_a[k0 + 2], aff_b[k0 + 2]), 0.f);
        v.w = fmaxf(fmaf(v.w, aff_a[k0 + 3], aff_b[k0 + 3]), 0.f);
        ((float4*)As)[idx] = v;
    }
    __syncthreads();

    int tx = tid & 15, ty = tid >> 4;
    unsigned long long acc[8][4];
    #pragma unroll
    for (int i = 0; i < 8; i++)
        #pragma unroll
        for (int j = 0; j < 4; j++) acc[i][j] = 0ULL;

    const float* Ab = As + ty * 8 * 128;
    #pragma unroll 8
    for (int k = 0; k < 128; k++) {
        const unsigned long long* bp = (const unsigned long long*)(Bs + k * 128) + tx * 4;
        ulonglong2 q0 = *(const ulonglong2*)bp;
        ulonglong2 q1 = *(const ulonglong2*)(bp + 2);
        unsigned long long bb0 = q0.x, bb1 = q0.y, bb2 = q1.x, bb3 = q1.y;
        #pragma unroll
        for (int i = 0; i < 8; i++) {
            unsigned long long aa = pack2(Ab[i * 128 + k]);
            ffma2(acc[i][0], aa, bb0);
            ffma2(acc[i][1], aa, bb1);
            ffma2(acc[i][2], aa, bb2);
            ffma2(acc[i][3], aa, bb3);
        }
    }
    __syncthreads();  // done reading As

    float b2l[8];
    #pragma unroll
    for (int j = 0; j < 8; j++) b2l[j] = b2[tx * 8 + j];

    // biased values + row partial sums; keep values in hv[][] (register)
    float hv[8][8];
    float rsum[8], rsq[8];
    #pragma unroll
    for (int i = 0; i < 8; i++) {
        rsum[i] = 0.f; rsq[i] = 0.f;
        #pragma unroll
        for (int j4 = 0; j4 < 4; j4++) {
            float2 f = unpack2(acc[i][j4]);
            float v0 = f.x + b2l[2 * j4];
            float v1 = f.y + b2l[2 * j4 + 1];
            hv[i][2 * j4] = v0; hv[i][2 * j4 + 1] = v1;
            rsum[i] += v0 + v1;
            rsq[i]  += v0 * v0 + v1 * v1;
        }
    }

    float* redS = As;               // [128][16]
    float* redQ = As + 2048;        // [128][16]
    float* rowM = As + 4096;        // [128]
    float* rowR = As + 4224;        // [128]
    #pragma unroll
    for (int i = 0; i < 8; i++) {
        redS[(ty * 8 + i) * 16 + tx] = rsum[i];
        redQ[(ty * 8 + i) * 16 + tx] = rsq[i];
    }
    __syncthreads();
    if (tid < 128) {
        float s = 0.f, q = 0.f;
        #pragma unroll
        for (int t = 0; t < 16; t++) { s += redS[tid * 16 + t]; q += redQ[tid * 16 + t]; }
        float m = s * (1.f / 128.f);
        float v = q * (1.f / 128.f) - m * m;
        rowM[tid] = m;
        rowR[tid] = rsqrtf(v + LN_EPS);
    }
    __syncthreads();

    #pragma unroll
    for (int i = 0; i < 8; i++) {
        int grow = row0 + ty * 8 + i;
        if (grow < N_NODES) {
            float m = rowM[ty * 8 + i];
            float r = rowR[ty * 8 + i];
            float o[8];
            #pragma unroll
            for (int j = 0; j < 8; j++) {
                int c = tx * 8 + j;
                float h = (hv[i][j] - m) * r * s_lng[c] + s_lnb[c];
                o[j] = (h >= 0.f) ? h : 0.1f * h;
            }
            float* op = d_A + (size_t)grow * 128 + tx * 8;
            ((float4*)op)[0] = make_float4(o[0], o[1], o[2], o[3]);
            ((float4*)(op + 4))[0] = make_float4(o[4], o[5], o[6], o[7]);
        }
    }
}

// ---------------- pooling: sorted-batch segment max/sum/count ----------------
__device__ __forceinline__ void atomicMaxFloat(float* addr, float val) {
    if (val >= 0.f) atomicMax((int*)addr, __float_as_int(val));
    else            atomicMin((unsigned int*)addr, __float_as_uint(val));
}

#define PROWS 512
__global__ void k_pool(const int* __restrict__ batch) {
    __shared__ int sb[PROWS];
    int r0 = blockIdx.x * PROWS;
    int r1 = min(r0 + PROWS, N_NODES);
    int c = threadIdx.x;
    int is64 = d_b64;
    for (int r = r0 + threadIdx.x; r < r1; r += 128)
        sb[r - r0] = is64 ? (int)((const long long*)batch)[r] : batch[r];
    __syncthreads();

    int gcur = -1, cnt = 0;
    float mx = -INFINITY, smv = 0.f;
    for (int r = r0; r < r1; r++) {
        int g = sb[r - r0];
        if (g != gcur) {
            if (gcur >= 0) {
                atomicMaxFloat(&d_gmax[gcur * 128 + c], mx);
                atomicAdd(&d_gsum[gcur * 128 + c], smv);
                if (c == 0) atomicAdd(&d_gcnt[gcur], cnt);
            }
            gcur = g; mx = -INFINITY; smv = 0.f; cnt = 0;
        }
        float v = d_A[(size_t)r * 128 + c];
        mx = fmaxf(mx, v);
        smv += v;
        cnt++;
    }
    if (gcur >= 0) {
        atomicMaxFloat(&d_gmax[gcur * 128 + c], mx);
        atomicAdd(&d_gsum[gcur * 128 + c], smv);
        if (c == 0) atomicAdd(&d_gcnt[gcur], cnt);
    }
}

// ---------------- final projection: out = [gmax || gmean] @ Wout + bout ----------------
__global__ void k_final(const float* __restrict__ Wout, const float* __restrict__ bout,
                        float* __restrict__ out) {
    __shared__ float pm[128], pa[128];
    int g = blockIdx.x, j = threadIdx.x;
    float cf = fmaxf((float)d_gcnt[g], 1.f);
    pm[j] = d_gmax[g * 128 + j];
    pa[j] = d_gsum[g * 128 + j] / cf;
    __syncthreads();
    float acc = bout[j];
    #pragma unroll 4
    for (int k = 0; k < 128; k++) acc = fmaf(pm[k], Wout[k * 128 + j], acc);
    #pragma unroll 4
    for (int k = 0; k < 128; k++) acc = fmaf(pa[k], Wout[(k + 128) * 128 + j], acc);
    out[g * 128 + j] = acc;
}

// ---------------- host launch ----------------
extern "C" void kernel_launch(void* const* d_in, const int* in_sizes, int n_in,
                              void* d_out, int out_size) {
    const float* x    = (const float*)d_in[0];
    const float* W1   = (const float*)d_in[1];
    const float* b1   = (const float*)d_in[2];
    const float* bn_g = (const float*)d_in[3];
    const float* bn_b = (const float*)d_in[4];
    const float* W2   = (const float*)d_in[5];
    const float* b2   = (const float*)d_in[6];
    const float* geps = (const float*)d_in[7];
    const float* ln_g = (const float*)d_in[8];
    const float* ln_b = (const float*)d_in[9];
    const float* Wout = (const float*)d_in[10];
    const float* bout = (const float*)d_in[11];
    const int*   ei   = (const int*)d_in[12];
    const int*   batch= (const int*)d_in[13];
    float* out = (float*)d_out;

    const int SMEMSZ = 136 * 1024;
    cudaFuncSetAttribute(k_gemm_bn, cudaFuncAttributeMaxDynamicSharedMemorySize, SMEMSZ);
    cudaFuncSetAttribute(k_gemm_ln, cudaFuncAttributeMaxDynamicSharedMemorySize, SMEMSZ);

    k_init<<<(N_NODES + 255) / 256, 256>>>();
    k_detect<<<1, 256>>>(ei, batch);

    // CSR build (per-call; deterministic)
    k_hist<<<(N_EDGES + 255) / 256, 256>>>(ei);
    k_scan<<<1, 1024>>>();
    k_fill<<<(N_EDGES + 255) / 256, 256>>>(ei);

    const int NBLK = (N_NODES + 127) / 128;          // 782
    for (int l = 0; l < NL; l++) {
        k_agg<<<(N_NODES * 32 + 255) / 256, 256>>>(x, geps, l);
        k_gemm_bn<<<NBLK, 256, SMEMSZ>>>(W1 + (size_t)l * DIM * DIM, b1 + l * DIM, l);
        k_gemm_ln<<<NBLK, 256, SMEMSZ>>>(W2 + (size_t)l * DIM * DIM, b2 + l * DIM,
                                         bn_g + l * DIM, bn_b + l * DIM,
                                         ln_g + l * DIM, ln_b + l * DIM, l);
    }
    k_pool<<<(N_NODES + PROWS - 1) / PROWS, 128>>>(batch);
    k_final<<<NG, 128>>>(Wout, bout, out);
}

// round 3
// speedup vs baseline: 1.3892x; 1.1413x over previous
#include <cuda_runtime.h>
#include <math.h>
#include <stdint.h>

#define N_NODES 100000
#define N_EDGES 1600000
#define DIM 128
#define NL 3
#define NG 256
#define BN_EPS 1e-5f
#define LN_EPS 1e-5f

#define SCAN_CHUNK 512
#define N_CHUNKS ((N_NODES + SCAN_CHUNK - 1) / SCAN_CHUNK)   // 196

// ---------------- scratch (static device globals; no allocation) ----------------
__device__ __align__(16) float d_A[N_NODES * DIM];    // current node features (layer output)
__device__ __align__(16) float d_Bagg[N_NODES * DIM]; // (1+eps)*x + neighbor sum
__device__ __align__(16) float d_C[N_NODES * DIM];    // post-GEMM1 hidden
__device__ float d_stats[NL * 2 * DIM];               // per-layer BN sum / sumsq
__device__ float d_gmax[NG * DIM];
__device__ float d_gsum[NG * DIM];
__device__ int   d_gcnt[NG];
__device__ int   d_ei64;   // 1 if edge_index is int64
__device__ int   d_b64;    // 1 if batch is int64
// CSR scratch
__device__ int d_deg[N_NODES];
__device__ int d_off[N_NODES + 1];
__device__ int d_cur[N_NODES];
__device__ int d_csr[N_EDGES];
__device__ int d_chunksum[N_CHUNKS];
__device__ int d_chunkoff[N_CHUNKS];

// ---------------- f32x2 helpers ----------------
__device__ __forceinline__ unsigned long long pack2(float a) {
    unsigned long long r;
    asm("mov.b64 %0, {%1, %1};" : "=l"(r) : "f"(a));
    return r;
}
__device__ __forceinline__ void ffma2(unsigned long long& d, unsigned long long a,
                                      unsigned long long b) {
    asm("fma.rn.f32x2 %0, %1, %2, %0;" : "+l"(d) : "l"(a), "l"(b));
}
__device__ __forceinline__ float2 unpack2(unsigned long long u) {
    float2 f;
    asm("mov.b64 {%0, %1}, %2;" : "=f"(f.x), "=f"(f.y) : "l"(u));
    return f;
}

// ---------------- init ----------------
__global__ void k_init() {
    int i = blockIdx.x * blockDim.x + threadIdx.x;
    if (i < NL * 2 * DIM) d_stats[i] = 0.f;
    if (i < NG * DIM) { d_gmax[i] = -INFINITY; d_gsum[i] = 0.f; }
    if (i < NG) d_gcnt[i] = 0;
    if (i < N_NODES) d_deg[i] = 0;
}

// ---------------- dtype probe (int32 vs int64) ----------------
__global__ void k_detect(const int* __restrict__ ei, const int* __restrict__ batch) {
    __shared__ int s1, s2;
    if (threadIdx.x == 0) { s1 = 0; s2 = 0; }
    __syncthreads();
    for (int i = threadIdx.x; i < 10000; i += blockDim.x) {
        if (ei[2 * i + 1] != 0)    atomicOr(&s1, 1);
        if (batch[2 * i + 1] != 0) atomicOr(&s2, 1);
    }
    __syncthreads();
    if (threadIdx.x == 0) { d_ei64 = s1 ? 0 : 1; d_b64 = s2 ? 0 : 1; }
}

// ---------------- CSR build ----------------
__global__ void k_hist(const int* __restrict__ ei) {
    int i = blockIdx.x * blockDim.x + threadIdx.x;
    if (i >= N_EDGES) return;
    int dst;
    if (d_ei64) dst = (int)((const long long*)ei)[N_EDGES + i];
    else        dst = ei[N_EDGES + i];
    atomicAdd(&d_deg[dst], 1);
}

// phase 1: per-chunk degree sums (196 blocks x 512)
__global__ void k_scan1() {
    __shared__ int sh[SCAN_CHUNK];
    int c = blockIdx.x, t = threadIdx.x;
    int i = c * SCAN_CHUNK + t;
    sh[t] = (i < N_NODES) ? d_deg[i] : 0;
    __syncthreads();
    #pragma unroll
    for (int o = SCAN_CHUNK / 2; o > 0; o >>= 1) {
        if (t < o) sh[t] += sh[t + o];
        __syncthreads();
    }
    if (t == 0) d_chunksum[c] = sh[0];
}

// phase 2: exclusive scan of chunk sums (1 block x 256)
__global__ void k_scan2() {
    __shared__ int sh[256];
    int t = threadIdx.x;
    int v = (t < N_CHUNKS) ? d_chunksum[t] : 0;
    sh[t] = v;
    __syncthreads();
    #pragma unroll
    for (int o = 1; o < 256; o <<= 1) {
        int u = (t >= o) ? sh[t - o] : 0;
        __syncthreads();
        sh[t] += u;
        __syncthreads();
    }
    if (t < N_CHUNKS) d_chunkoff[t] = sh[t] - v;   // exclusive prefix
}

// phase 3: intra-chunk exclusive scan + chunk offset (196 blocks x 512)
__global__ void k_scan3() {
    __shared__ int sh[SCAN_CHUNK];
    int c = blockIdx.x, t = threadIdx.x;
    int i = c * SCAN_CHUNK + t;
    int v = (i < N_NODES) ? d_deg[i] : 0;
    sh[t] = v;
    __syncthreads();
    #pragma unroll
    for (int o = 1; o < SCAN_CHUNK; o <<= 1) {
        int u = (t >= o) ? sh[t - o] : 0;
        __syncthreads();
        sh[t] += u;
        __syncthreads();
    }
    int excl = sh[t] - v + d_chunkoff[c];
    if (i < N_NODES) { d_off[i] = excl; d_cur[i] = excl; }
    if (i == N_NODES - 1) d_off[N_NODES] = excl + v;
}

__global__ void k_fill(const int* __restrict__ ei) {
    int i = blockIdx.x * blockDim.x + threadIdx.x;
    if (i >= N_EDGES) return;
    int src, dst;
    if (d_ei64) {
        const long long* e64 = (const long long*)ei;
        src = (int)e64[i];
        dst = (int)e64[N_EDGES + i];
    } else {
        src = ei[i];
        dst = ei[N_EDGES + i];
    }
    int pos = atomicAdd(&d_cur[dst], 1);
    d_csr[pos] = src;
}

// ---------------- aggregation: warp per node, register accumulation ----------------
__global__ void k_agg(const float* __restrict__ x, const float* __restrict__ geps, int l) {
    int w = (blockIdx.x * blockDim.x + threadIdx.x) >> 5;
    int lane = threadIdx.x & 31;
    if (w >= N_NODES) return;
    const float* cur = (l == 0) ? x : d_A;
    float s = 1.f + geps[l];
    float4 acc = ((const float4*)cur)[(size_t)w * 32 + lane];
    acc.x *= s; acc.y *= s; acc.z *= s; acc.w *= s;
    int beg = d_off[w], end = d_off[w + 1];
    for (int base = beg; base < end; base += 32) {
        int idx = 0;
        if (base + lane < end) idx = d_csr[base + lane];
        int n = min(32, end - base);
        for (int t = 0; t < n; t++) {
            int sidx = __shfl_sync(0xffffffff, idx, t);
            float4 v = ((const float4*)cur)[(size_t)sidx * 32 + lane];
            acc.x += v.x; acc.y += v.y; acc.z += v.z; acc.w += v.w;
        }
    }
    ((float4*)d_Bagg)[(size_t)w * 32 + lane] = acc;
}

// ---------------- GEMM1: C = Bagg @ W1[l] + b1[l], fused BN-stat accumulation ----------------
__global__ void __launch_bounds__(256, 1)
k_gemm_bn(const float* __restrict__ W, const float* __restrict__ bias, int l) {
    extern __shared__ float smem[];
    float* As = smem;            // 128*128
    float* Bs = smem + 16384;    // 128*128
    const float* X = d_Bagg;
    int tid = threadIdx.x;
    int row0 = blockIdx.x * 128;

    #pragma unroll
    for (int i = 0; i < 16; i++) {
        int idx = tid + i * 256;
        ((float4*)Bs)[idx] = ((const float4*)W)[idx];
    }
    #pragma unroll
    for (int i = 0; i < 16; i++) {
        int idx = tid + i * 256;
        int r = idx >> 5, c4 = idx & 31;
        int grow = row0 + r;
        float4 v = make_float4(0.f, 0.f, 0.f, 0.f);
        if (grow < N_NODES) v = ((const float4*)X)[grow * 32 + c4];
        ((float4*)As)[idx] = v;
    }
    __syncthreads();

    int tx = tid & 15, ty = tid >> 4;
    unsigned long long acc[8][4];
    #pragma unroll
    for (int i = 0; i < 8; i++)
        #pragma unroll
        for (int j = 0; j < 4; j++) acc[i][j] = 0ULL;

    const float* Ab = As + ty * 8 * 128;
    #pragma unroll 8
    for (int k = 0; k < 128; k++) {
        const unsigned long long* bp = (const unsigned long long*)(Bs + k * 128) + tx * 4;
        ulonglong2 q0 = *(const ulonglong2*)bp;
        ulonglong2 q1 = *(const ulonglong2*)(bp + 2);
        unsigned long long bb0 = q0.x, bb1 = q0.y, bb2 = q1.x, bb3 = q1.y;
        #pragma unroll
        for (int i = 0; i < 8; i++) {
            unsigned long long aa = pack2(Ab[i * 128 + k]);
            ffma2(acc[i][0], aa, bb0);
            ffma2(acc[i][1], aa, bb1);
            ffma2(acc[i][2], aa, bb2);
            ffma2(acc[i][3], aa, bb3);
        }
    }
    __syncthreads();   // done reading As; reuse it below

    float bl[8];
    #pragma unroll
    for (int j = 0; j < 8; j++) bl[j] = bias[tx * 8 + j];
    float cs[8], cq[8];
    #pragma unroll
    for (int j = 0; j < 8; j++) { cs[j] = 0.f; cq[j] = 0.f; }

    #pragma unroll
    for (int i = 0; i < 8; i++) {
        int grow = row0 + ty * 8 + i;
        if (grow < N_NODES) {
            float v[8];
            #pragma unroll
            for (int j4 = 0; j4 < 4; j4++) {
                float2 f = unpack2(acc[i][j4]);
                v[2 * j4] = f.x + bl[2 * j4];
                v[2 * j4 + 1] = f.y + bl[2 * j4 + 1];
            }
            #pragma unroll
            for (int j = 0; j < 8; j++) { cs[j] += v[j]; cq[j] += v[j] * v[j]; }
            float* op = d_C + (size_t)grow * 128 + tx * 8;
            ((float4*)op)[0] = make_float4(v[0], v[1], v[2], v[3]);
            ((float4*)(op + 4))[0] = make_float4(v[4], v[5], v[6], v[7]);
        }
    }

    float* rs = As;               // [16][128]
    float* rq = As + 16 * 128;    // [16][128]
    #pragma unroll
    for (int j = 0; j < 8; j++) {
        rs[ty * 128 + tx * 8 + j] = cs[j];
        rq[ty * 128 + tx * 8 + j] = cq[j];
    }
    __syncthreads();
    if (tid < 128) {
        float s = 0.f, q = 0.f;
        #pragma unroll
        for (int t = 0; t < 16; t++) { s += rs[t * 128 + tid]; q += rq[t * 128 + tid]; }
        atomicAdd(&d_stats[l * 2 * DIM + tid], s);
        atomicAdd(&d_stats[l * 2 * DIM + DIM + tid], q);
    }
}

// ---------------- GEMM2: A = leaky(LN( relu(BN(C)) @ W2[l] + b2[l] )) ----------------
__global__ void __launch_bounds__(256, 1)
k_gemm_ln(const float* __restrict__ W, const float* __restrict__ b2,
          const float* __restrict__ bn_g, const float* __restrict__ bn_b,
          const float* __restrict__ ln_g, const float* __restrict__ ln_b, int l) {
    extern __shared__ float smem[];
    float* As    = smem;              // 128*128
    float* Bs    = smem + 16384;      // 128*128
    float* aff_a = smem + 32768;      // 128
    float* aff_b = aff_a + 128;       // 128
    float* s_lng = aff_b + 128;       // 128
    float* s_lnb = s_lng + 128;       // 128
    const float* X = d_C;
    int tid = threadIdx.x;
    int row0 = blockIdx.x * 128;

    if (tid < 128) {
        float mu  = d_stats[l * 2 * DIM + tid] * (1.f / N_NODES);
        float var = d_stats[l * 2 * DIM + DIM + tid] * (1.f / N_NODES) - mu * mu;
        float rstd = rsqrtf(var + BN_EPS);
        float a = bn_g[tid] * rstd;
        aff_a[tid] = a;
        aff_b[tid] = bn_b[tid] - mu * a;
        s_lng[tid] = ln_g[tid];
        s_lnb[tid] = ln_b[tid];
    }
    __syncthreads();

    #pragma unroll
    for (int i = 0; i < 16; i++) {
        int idx = tid + i * 256;
        ((float4*)Bs)[idx] = ((const float4*)W)[idx];
    }
    #pragma unroll
    for (int i = 0; i < 16; i++) {
        int idx = tid + i * 256;
        int r = idx >> 5, c4 = idx & 31;
        int grow = row0 + r;
        float4 v = make_float4(0.f, 0.f, 0.f, 0.f);
        if (grow < N_NODES) v = ((const float4*)X)[grow * 32 + c4];
        int k0 = c4 * 4;
        v.x = fmaxf(fmaf(v.x, aff_a[k0 + 0], aff_b[k0 + 0]), 0.f);
        v.y = fmaxf(fmaf(v.y, aff_a[k0 + 1], aff_b[k0 + 1]), 0.f);
        v.z = fmaxf(fmaf(v.z, aff_a[k0 + 2], aff_b[k0 + 2]), 0.f);
        v.w = fmaxf(fmaf(v.w, aff_a[k0 + 3], aff_b[k0 + 3]), 0.f);
        ((float4*)As)[idx] = v;
    }
    __syncthreads();

    int tx = tid & 15, ty = tid >> 4;
    unsigned long long acc[8][4];
    #pragma unroll
    for (int i = 0; i < 8; i++)
        #pragma unroll
        for (int j = 0; j < 4; j++) acc[i][j] = 0ULL;

    const float* Ab = As + ty * 8 * 128;
    #pragma unroll 8
    for (int k = 0; k < 128; k++) {
        const unsigned long long* bp = (const unsigned long long*)(Bs + k * 128) + tx * 4;
        ulonglong2 q0 = *(const ulonglong2*)bp;
        ulonglong2 q1 = *(const ulonglong2*)(bp + 2);
        unsigned long long bb0 = q0.x, bb1 = q0.y, bb2 = q1.x, bb3 = q1.y;
        #pragma unroll
        for (int i = 0; i < 8; i++) {
            unsigned long long aa = pack2(Ab[i * 128 + k]);
            ffma2(acc[i][0], aa, bb0);
            ffma2(acc[i][1], aa, bb1);
            ffma2(acc[i][2], aa, bb2);
            ffma2(acc[i][3], aa, bb3);
        }
    }
    __syncthreads();  // done reading As

    float b2l[8];
    #pragma unroll
    for (int j = 0; j < 8; j++) b2l[j] = b2[tx * 8 + j];

    float hv[8][8];
    float rsum[8], rsq[8];
    #pragma unroll
    for (int i = 0; i < 8; i++) {
        rsum[i] = 0.f; rsq[i] = 0.f;
        #pragma unroll
        for (int j4 = 0; j4 < 4; j4++) {
            float2 f = unpack2(acc[i][j4]);
            float v0 = f.x + b2l[2 * j4];
            float v1 = f.y + b2l[2 * j4 + 1];
            hv[i][2 * j4] = v0; hv[i][2 * j4 + 1] = v1;
            rsum[i] += v0 + v1;
            rsq[i]  += v0 * v0 + v1 * v1;
        }
    }

    float* redS = As;               // [128][16]
    float* redQ = As + 2048;        // [128][16]
    float* rowM = As + 4096;        // [128]
    float* rowR = As + 4224;        // [128]
    #pragma unroll
    for (int i = 0; i < 8; i++) {
        redS[(ty * 8 + i) * 16 + tx] = rsum[i];
        redQ[(ty * 8 + i) * 16 + tx] = rsq[i];
    }
    __syncthreads();
    if (tid < 128) {
        float s = 0.f, q = 0.f;
        #pragma unroll
        for (int t = 0; t < 16; t++) { s += redS[tid * 16 + t]; q += redQ[tid * 16 + t]; }
        float m = s * (1.f / 128.f);
        float v = q * (1.f / 128.f) - m * m;
        rowM[tid] = m;
        rowR[tid] = rsqrtf(v + LN_EPS);
    }
    __syncthreads();

    #pragma unroll
    for (int i = 0; i < 8; i++) {
        int grow = row0 + ty * 8 + i;
        if (grow < N_NODES) {
            float m = rowM[ty * 8 + i];
            float r = rowR[ty * 8 + i];
            float o[8];
            #pragma unroll
            for (int j = 0; j < 8; j++) {
                int c = tx * 8 + j;
                float h = (hv[i][j] - m) * r * s_lng[c] + s_lnb[c];
                o[j] = (h >= 0.f) ? h : 0.1f * h;
            }
            float* op = d_A + (size_t)grow * 128 + tx * 8;
            ((float4*)op)[0] = make_float4(o[0], o[1], o[2], o[3]);
            ((float4*)(op + 4))[0] = make_float4(o[4], o[5], o[6], o[7]);
        }
    }
}

// ---------------- pooling: sorted-batch segment max/sum/count ----------------
__device__ __forceinline__ void atomicMaxFloat(float* addr, float val) {
    if (val >= 0.f) atomicMax((int*)addr, __float_as_int(val));
    else            atomicMin((unsigned int*)addr, __float_as_uint(val));
}

#define PROWS 512
__global__ void k_pool(const int* __restrict__ batch) {
    __shared__ int sb[PROWS];
    int r0 = blockIdx.x * PROWS;
    int r1 = min(r0 + PROWS, N_NODES);
    int c = threadIdx.x;
    int is64 = d_b64;
    for (int r = r0 + threadIdx.x; r < r1; r += 128)
        sb[r - r0] = is64 ? (int)((const long long*)batch)[r] : batch[r];
    __syncthreads();

    int gcur = -1, cnt = 0;
    float mx = -INFINITY, smv = 0.f;
    for (int r = r0; r < r1; r++) {
        int g = sb[r - r0];
        if (g != gcur) {
            if (gcur >= 0) {
                atomicMaxFloat(&d_gmax[gcur * 128 + c], mx);
                atomicAdd(&d_gsum[gcur * 128 + c], smv);
                if (c == 0) atomicAdd(&d_gcnt[gcur], cnt);
            }
            gcur = g; mx = -INFINITY; smv = 0.f; cnt = 0;
        }
        float v = d_A[(size_t)r * 128 + c];
        mx = fmaxf(mx, v);
        smv += v;
        cnt++;
    }
    if (gcur >= 0) {
        atomicMaxFloat(&d_gmax[gcur * 128 + c], mx);
        atomicAdd(&d_gsum[gcur * 128 + c], smv);
        if (c == 0) atomicAdd(&d_gcnt[gcur], cnt);
    }
}

// ---------------- final projection: out = [gmax || gmean] @ Wout + bout ----------------
__global__ void k_final(const float* __restrict__ Wout, const float* __restrict__ bout,
                        float* __restrict__ out) {
    __shared__ float pm[128], pa[128];
    int g = blockIdx.x, j = threadIdx.x;
    float cf = fmaxf((float)d_gcnt[g], 1.f);
    pm[j] = d_gmax[g * 128 + j];
    pa[j] = d_gsum[g * 128 + j] / cf;
    __syncthreads();
    float acc = bout[j];
    #pragma unroll 4
    for (int k = 0; k < 128; k++) acc = fmaf(pm[k], Wout[k * 128 + j], acc);
    #pragma unroll 4
    for (int k = 0; k < 128; k++) acc = fmaf(pa[k], Wout[(k + 128) * 128 + j], acc);
    out[g * 128 + j] = acc;
}

// ---------------- host launch ----------------
extern "C" void kernel_launch(void* const* d_in, const int* in_sizes, int n_in,
                              void* d_out, int out_size) {
    const float* x    = (const float*)d_in[0];
    const float* W1   = (const float*)d_in[1];
    const float* b1   = (const float*)d_in[2];
    const float* bn_g = (const float*)d_in[3];
    const float* bn_b = (const float*)d_in[4];
    const float* W2   = (const float*)d_in[5];
    const float* b2   = (const float*)d_in[6];
    const float* geps = (const float*)d_in[7];
    const float* ln_g = (const float*)d_in[8];
    const float* ln_b = (const float*)d_in[9];
    const float* Wout = (const float*)d_in[10];
    const float* bout = (const float*)d_in[11];
    const int*   ei   = (const int*)d_in[12];
    const int*   batch= (const int*)d_in[13];
    float* out = (float*)d_out;

    const int SMEMSZ = 136 * 1024;
    cudaFuncSetAttribute(k_gemm_bn, cudaFuncAttributeMaxDynamicSharedMemorySize, SMEMSZ);
    cudaFuncSetAttribute(k_gemm_ln, cudaFuncAttributeMaxDynamicSharedMemorySize, SMEMSZ);

    k_init<<<(N_NODES + 255) / 256, 256>>>();
    k_detect<<<1, 256>>>(ei, batch);

    // CSR build (per-call; deterministic up to fp-benign edge order)
    k_hist<<<(N_EDGES + 255) / 256, 256>>>(ei);
    k_scan1<<<N_CHUNKS, SCAN_CHUNK>>>();
    k_scan2<<<1, 256>>>();
    k_scan3<<<N_CHUNKS, SCAN_CHUNK>>>();
    k_fill<<<(N_EDGES + 255) / 256, 256>>>(ei);

    const int NBLK = (N_NODES + 127) / 128;          // 782
    for (int l = 0; l < NL; l++) {
        k_agg<<<(N_NODES * 32 + 255) / 256, 256>>>(x, geps, l);
        k_gemm_bn<<<NBLK, 256, SMEMSZ>>>(W1 + (size_t)l * DIM * DIM, b1 + l * DIM, l);
        k_gemm_ln<<<NBLK, 256, SMEMSZ>>>(W2 + (size_t)l * DIM * DIM, b2 + l * DIM,
                                         bn_g + l * DIM, bn_b + l * DIM,
                                         ln_g + l * DIM, ln_b + l * DIM, l);
    }
    k_pool<<<(N_NODES + PROWS - 1) / PROWS, 128>>>(batch);
    k_final<<<NG, 128>>>(Wout, bout, out);
}